// round 4
// baseline (speedup 1.0000x reference)
#include <cuda_runtime.h>
#include <math.h>

#define TILE_PTS 2048   // 32 KB of float4

__global__ void zero_kernel(float* out, int n) {
    int i = blockIdx.x * blockDim.x + threadIdx.x;
    if (i < n) out[i] = 0.0f;
}

// For each query point n (one thread each), count padding points m with
//   d2 = ||q||^2 + ||p||^2 - 2 q.p  <= 0.25
// (exactly the reference's sqrt(max(d2,0)) <= 0.5: sqrt monotone, 0.25 exact).
// M is split across blockIdx.y; partial counts accumulate via float atomics
// (exact: small integers, disjoint addresses per n).
__global__ void __launch_bounds__(256) count_kernel(
    const float* __restrict__ pc,   // queries [N,3]
    const float* __restrict__ pad,  // padding [M,3]
    int N, int M, int tile_pts, float* __restrict__ out)
{
    __shared__ float4 sh[TILE_PTS];

    int m0 = blockIdx.y * tile_pts;
    int np = M - m0;
    if (np > tile_pts) np = tile_pts;

    // Stage this block's padding slice: {x, y, z, ||p||^2}
    for (int i = threadIdx.x; i < np; i += 256) {
        int m = m0 + i;
        float ax = pad[3 * m], ay = pad[3 * m + 1], az = pad[3 * m + 2];
        float a2 = fmaf(ax, ax, fmaf(ay, ay, az * az));
        sh[i] = make_float4(ax, ay, az, a2);
    }
    __syncthreads();

    int n = blockIdx.x * 256 + threadIdx.x;
    float bx = 0.f, by = 0.f, bz = 0.f;
    float b2 = __int_as_float(0x7f800000);  // +inf: inactive threads never count
    if (n < N) {
        bx = pc[3 * n]; by = pc[3 * n + 1]; bz = pc[3 * n + 2];
        b2 = fmaf(bx, bx, fmaf(by, by, bz * bz));
    }

    int cnt = 0;
#pragma unroll 8
    for (int j = 0; j < np; ++j) {
        float4 w = sh[j];                                   // broadcast LDS.128
        float ab = fmaf(bx, w.x, fmaf(by, w.y, bz * w.z));  // q . p
        float d2 = fmaf(-2.0f, ab, b2 + w.w);               // a2+b2-2ab
        cnt += (d2 <= 0.25f) ? 1 : 0;
    }

    if (n < N) atomicAdd(out + n, (float)cnt);
}

extern "C" void kernel_launch(void* const* d_in, const int* in_sizes, int n_in,
                              void* d_out, int out_size) {
    // Output has one row per pointcloud point => the input with 3*out_size
    // elements IS the pointcloud, regardless of metadata ordering.
    int N = out_size;
    const float* pc;
    const float* pad;
    int M;
    if (in_sizes[0] == 3 * out_size) {
        pc  = (const float*)d_in[0];
        pad = (const float*)d_in[1];
        M   = in_sizes[1] / 3;
    } else {
        pc  = (const float*)d_in[1];
        pad = (const float*)d_in[0];
        M   = in_sizes[0] / 3;
    }

    int msplit   = (M + TILE_PTS - 1) / TILE_PTS;  // 13 for M=25000
    if (msplit < 1) msplit = 1;
    int tile_pts = (M + msplit - 1) / msplit;      // 1924

    float* out = (float*)d_out;
    zero_kernel<<<(out_size + 255) / 256, 256>>>(out, out_size);
    dim3 grid((N + 255) / 256, msplit);
    count_kernel<<<grid, 256>>>(pc, pad, N, M, tile_pts, out);
}

// round 5
// speedup vs baseline: 1.0015x; 1.0015x over previous
#include <cuda_runtime.h>
#include <math.h>

#define TILE_PTS 2048   // 32 KB of float4

__global__ void zero_kernel(float* out, int n) {
    int i = blockIdx.x * blockDim.x + threadIdx.x;
    if (i < n) out[i] = 0.0f;
}

// For each query point n (one thread each), count padding points m with
//   d2 = ||q||^2 + ||p||^2 - 2 q.p  <= 0.25
// (exactly the reference's sqrt(max(d2,0)) <= 0.5: sqrt monotone, 0.25 exact).
// M is split across blockIdx.y; partial counts accumulate via float atomics
// (exact: small integers, disjoint addresses per n).
__global__ void __launch_bounds__(256) count_kernel(
    const float* __restrict__ pc,   // queries [N,3]
    const float* __restrict__ pad,  // padding [M,3]
    int N, int M, int tile_pts, float* __restrict__ out)
{
    __shared__ float4 sh[TILE_PTS];

    int m0 = blockIdx.y * tile_pts;
    int np = M - m0;
    if (np > tile_pts) np = tile_pts;

    // Stage this block's padding slice: {x, y, z, ||p||^2}
    for (int i = threadIdx.x; i < np; i += 256) {
        int m = m0 + i;
        float ax = pad[3 * m], ay = pad[3 * m + 1], az = pad[3 * m + 2];
        float a2 = fmaf(ax, ax, fmaf(ay, ay, az * az));
        sh[i] = make_float4(ax, ay, az, a2);
    }
    __syncthreads();

    int n = blockIdx.x * 256 + threadIdx.x;
    float bx = 0.f, by = 0.f, bz = 0.f;
    float b2 = __int_as_float(0x7f800000);  // +inf: inactive threads never count
    if (n < N) {
        bx = pc[3 * n]; by = pc[3 * n + 1]; bz = pc[3 * n + 2];
        b2 = fmaf(bx, bx, fmaf(by, by, bz * bz));
    }

    int cnt = 0;
#pragma unroll 8
    for (int j = 0; j < np; ++j) {
        float4 w = sh[j];                                   // broadcast LDS.128
        float ab = fmaf(bx, w.x, fmaf(by, w.y, bz * w.z));  // q . p
        float d2 = fmaf(-2.0f, ab, b2 + w.w);               // a2+b2-2ab
        cnt += (d2 <= 0.25f) ? 1 : 0;
    }

    if (n < N) atomicAdd(out + n, (float)cnt);
}

extern "C" void kernel_launch(void* const* d_in, const int* in_sizes, int n_in,
                              void* d_out, int out_size) {
    // Output has one row per pointcloud point => the input with 3*out_size
    // elements IS the pointcloud, regardless of metadata ordering.
    int N = out_size;
    const float* pc;
    const float* pad;
    int M;
    if (in_sizes[0] == 3 * out_size) {
        pc  = (const float*)d_in[0];
        pad = (const float*)d_in[1];
        M   = in_sizes[1] / 3;
    } else {
        pc  = (const float*)d_in[1];
        pad = (const float*)d_in[0];
        M   = in_sizes[0] / 3;
    }

    int msplit   = (M + TILE_PTS - 1) / TILE_PTS;  // 13 for M=25000
    if (msplit < 1) msplit = 1;
    int tile_pts = (M + msplit - 1) / msplit;      // 1924

    float* out = (float*)d_out;
    zero_kernel<<<(out_size + 255) / 256, 256>>>(out, out_size);
    dim3 grid((N + 255) / 256, msplit);
    count_kernel<<<grid, 256>>>(pc, pad, N, M, tile_pts, out);
}

// round 7
// speedup vs baseline: 1.2919x; 1.2900x over previous
#include <cuda_runtime.h>
#include <math.h>

#define TILE_PAIRS 1024        // smem capacity in packed m-pairs (32 KB)
#define MAX_PPS    1020        // <=255 loop iterations => byte counters never overflow
#define PAIRS_CAP  16384

typedef unsigned long long u64;
typedef unsigned int u32;

// Per m-pair p: [2p] = {X01, Y01}, [2p+1] = {Z01, C01}
// where X01 = pack(-2*x_{2p}, -2*x_{2p+1}) etc., C01 = pack(a2-0.25 for both lanes).
__device__ ulonglong2 g_packed[2 * PAIRS_CAP];

__device__ __forceinline__ u64 pk2(float a, float b) {
    u64 r; asm("mov.b64 %0, {%1, %2};" : "=l"(r) : "f"(a), "f"(b)); return r;
}
__device__ __forceinline__ void unpk2(u64 v, u32& lo, u32& hi) {
    asm("mov.b64 {%0, %1}, %2;" : "=r"(lo), "=r"(hi) : "l"(v));
}
__device__ __forceinline__ u64 fma2(u64 a, u64 b, u64 c) {
    u64 d; asm("fma.rn.f32x2 %0, %1, %2, %3;" : "=l"(d) : "l"(a), "l"(b), "l"(c)); return d;
}
__device__ __forceinline__ u64 add2(u64 a, u64 b) {
    u64 d; asm("add.rn.f32x2 %0, %1, %2;" : "=l"(d) : "l"(a), "l"(b)); return d;
}
__device__ __forceinline__ u32 prmt(u32 a, u32 b, u32 ctl) {
    u32 d; asm("prmt.b32 %0, %1, %2, %3;" : "=r"(d) : "r"(a), "r"(b), "r"(ctl)); return d;
}

__global__ void zero_kernel(float* out, int n) {
    int i = blockIdx.x * blockDim.x + threadIdx.x;
    if (i < n) out[i] = 0.0f;
}

__global__ void prep_kernel(const float* __restrict__ pad, int M, int pairs) {
    int p = blockIdx.x * blockDim.x + threadIdx.x;
    if (p >= pairs) return;
    int m0 = 2 * p, m1 = 2 * p + 1;
    float x0 = pad[3 * m0], y0 = pad[3 * m0 + 1], z0 = pad[3 * m0 + 2];
    float c0 = fmaf(x0, x0, fmaf(y0, y0, z0 * z0)) - 0.25f;
    float x1 = 0.f, y1 = 0.f, z1 = 0.f;
    float c1 = __int_as_float(0x7f800000);   // +inf sentinel: never counts
    if (m1 < M) {
        x1 = pad[3 * m1]; y1 = pad[3 * m1 + 1]; z1 = pad[3 * m1 + 2];
        c1 = fmaf(x1, x1, fmaf(y1, y1, z1 * z1)) - 0.25f;
    }
    g_packed[2 * p]     = make_ulonglong2(pk2(-2.f * x0, -2.f * x1), pk2(-2.f * y0, -2.f * y1));
    g_packed[2 * p + 1] = make_ulonglong2(pk2(-2.f * z0, -2.f * z1), pk2(c0, c1));
}

// Count condition: s = b2 + (a2 - 0.25) + (-2x)bx + (-2y)by + (-2z)bz = d2 - 0.25
// count iff sign(s) (s < 0, and -0.0 for exact ties). Matches reference's
// sqrt(max(d2,0)) <= 0.5 up to ulp-level reassociation ties.
__global__ void __launch_bounds__(256) count_kernel(
    const float* __restrict__ pc, int N, int pairs, int pps, float* __restrict__ out)
{
    __shared__ ulonglong2 sh[2 * TILE_PAIRS];   // 32 KB

    int p0 = blockIdx.y * pps;
    int np = pairs - p0;
    if (np > pps) np = pps;
    int np4 = (np + 3) & ~3;                    // pad to multiple of 4 pairs

    {   // stage packed pairs (contiguous 16B loads)
        const uint4* g  = reinterpret_cast<const uint4*>(g_packed + 2 * p0);
        uint4*       s4 = reinterpret_cast<uint4*>(sh);
        for (int i = threadIdx.x; i < 2 * np; i += 256) s4[i] = g[i];
    }
    // sentinel padding pairs (<=3)
    for (int j = np + threadIdx.x; j < np4; j += 256) {
        sh[2 * j]     = make_ulonglong2(0ull, 0ull);
        sh[2 * j + 1] = make_ulonglong2(0ull, pk2(__int_as_float(0x7f800000),
                                                  __int_as_float(0x7f800000)));
    }
    __syncthreads();

    int n = blockIdx.x * 256 + threadIdx.x;
    float bx = 0.f, by = 0.f, bz = 0.f;
    float b2 = __int_as_float(0x7f800000);      // +inf: inactive threads never count
    if (n < N) {
        bx = pc[3 * n]; by = pc[3 * n + 1]; bz = pc[3 * n + 2];
        b2 = fmaf(bx, bx, fmaf(by, by, bz * bz));
    }
    const u64 bx2 = pk2(bx, bx), by2 = pk2(by, by), bz2 = pk2(bz, bz), b2p = pk2(b2, b2);

    u32 acc_a = 0, acc_b = 0;
    const ulonglong2* shp = sh;
    for (int j = 0; j < np4; j += 4) {
        ulonglong2 A0 = shp[2 * j + 0], B0 = shp[2 * j + 1];
        ulonglong2 A1 = shp[2 * j + 2], B1 = shp[2 * j + 3];
        ulonglong2 A2 = shp[2 * j + 4], B2 = shp[2 * j + 5];
        ulonglong2 A3 = shp[2 * j + 6], B3 = shp[2 * j + 7];

        u64 s0 = add2(fma2(bz2, B0.x, fma2(by2, A0.y, fma2(bx2, A0.x, B0.y))), b2p);
        u64 s1 = add2(fma2(bz2, B1.x, fma2(by2, A1.y, fma2(bx2, A1.x, B1.y))), b2p);
        u64 s2 = add2(fma2(bz2, B2.x, fma2(by2, A2.y, fma2(bx2, A2.x, B2.y))), b2p);
        u64 s3 = add2(fma2(bz2, B3.x, fma2(by2, A3.y, fma2(bx2, A3.x, B3.y))), b2p);

        u32 l0, h0, l1, h1, l2, h2, l3, h3;
        unpk2(s0, l0, h0); unpk2(s1, l1, h1);
        unpk2(s2, l2, h2); unpk2(s3, l3, h3);

        // prmt msb-replicate: nibble 0xB = sign-fill from byte3(a), 0xF = byte7(b)
        u32 q0 = prmt(l0, h0, 0x00FB);          // bytes 0,1 = signs of pair j
        u32 q1 = prmt(l1, h1, 0xFB00);          // bytes 2,3 = signs of pair j+1
        acc_a += (q0 & 0x00000101u) + (q1 & 0x01010000u);
        u32 q2 = prmt(l2, h2, 0x00FB);
        u32 q3 = prmt(l3, h3, 0xFB00);
        acc_b += (q2 & 0x00000101u) + (q3 & 0x01010000u);
    }

    // Unsigned byte-field reduction (bytes <= 241; signed dp4a was the R6 bug)
    u32 cnt = (acc_a & 0xFFu) + ((acc_a >> 8) & 0xFFu)
            + ((acc_a >> 16) & 0xFFu) + (acc_a >> 24)
            + (acc_b & 0xFFu) + ((acc_b >> 8) & 0xFFu)
            + ((acc_b >> 16) & 0xFFu) + (acc_b >> 24);

    if (n < N) atomicAdd(out + n, (float)cnt);
}

extern "C" void kernel_launch(void* const* d_in, const int* in_sizes, int n_in,
                              void* d_out, int out_size) {
    // The input with 3*out_size elements IS the pointcloud (output rows = N).
    int N = out_size;
    const float* pc;
    const float* pad;
    int M;
    if (in_sizes[0] == 3 * out_size) {
        pc  = (const float*)d_in[0];
        pad = (const float*)d_in[1];
        M   = in_sizes[1] / 3;
    } else {
        pc  = (const float*)d_in[1];
        pad = (const float*)d_in[0];
        M   = in_sizes[0] / 3;
    }

    int pairs = (M + 1) / 2;
    if (pairs > PAIRS_CAP) pairs = PAIRS_CAP;   // capacity guard

    int msplit = (pairs + MAX_PPS - 1) / MAX_PPS;   // 13 for M=25000
    if (msplit < 1) msplit = 1;
    int pps = (pairs + msplit - 1) / msplit;        // 962

    float* out = (float*)d_out;
    zero_kernel<<<(out_size + 255) / 256, 256>>>(out, out_size);
    prep_kernel<<<(pairs + 255) / 256, 256>>>(pad, M, pairs);
    dim3 grid((N + 255) / 256, msplit);
    count_kernel<<<grid, 256>>>(pc, N, pairs, pps, out);
}